// round 9
// baseline (speedup 1.0000x reference)
#include <cuda_runtime.h>
#include <cstdint>

#define BATCH 8
#define NPTS  32768
#define DIM   256
#define SPTS  64
#define NS    8
#define R2    16.0f
#define FCTAS 8                 // CTAs per batch (cluster size)
#define SEG   (NPTS/FCTAS)      // 4096 points per CTA
#define FBLK  512
#define FPT   (SEG/FBLK)        // 8 points per thread

// ---------------- scratch (no allocations allowed) ----------------
__device__ float g_dcoor[BATCH*SPTS*3];
__device__ float g_kT[BATCH*DIM*SPTS];   // k transposed: [b][c][j]

// dynamic smem layout (floats)
#define SQ_OFF   0                        // sq[8][256]
#define RA_OFF   (8*DIM)                  // region A: sdiff/ssamp, later kts[256][64]
#define SD_OFF   RA_OFF                   // sdiff[8][256]
#define SS_OFF   (RA_OFF + 8*DIM)         // ssamp[8][256]
#define KT_OFF   RA_OFF                   // kts[256][64] (aliases sdiff/ssamp)
#define VS_OFF   (RA_OFF + DIM*SPTS)      // vs[192]
#define AT_OFF   (VS_OFF + 192)           // s_att[8][64]
#define DYN_FLOATS (AT_OFF + 8*64)
#define DYN_BYTES  (DYN_FLOATS * 4)

// ---------------- PTX helpers ----------------
__device__ __forceinline__ uint32_t smem_u32(const void* p) {
    uint32_t a;
    asm("{ .reg .u64 t; cvta.to.shared.u64 t, %1; cvt.u32.u64 %0, t; }" : "=r"(a) : "l"(p));
    return a;
}
__device__ __forceinline__ uint32_t mapa_rank(uint32_t a, uint32_t r) {
    uint32_t o;
    asm("mapa.shared::cluster.u32 %0, %1, %2;" : "=r"(o) : "r"(a), "r"(r));
    return o;
}
__device__ __forceinline__ void st_cluster_release_b64(uint32_t a, unsigned long long v) {
    asm volatile("st.release.cluster.shared::cluster.b64 [%0], %1;" :: "r"(a), "l"(v) : "memory");
}
__device__ __forceinline__ unsigned long long ld_acquire_b64(uint32_t a) {
    unsigned long long v;
    asm volatile("ld.acquire.cluster.shared::cta.b64 %0, [%1];" : "=l"(v) : "r"(a) : "memory");
    return v;
}
__device__ __forceinline__ unsigned long long ld_volatile_b64(uint32_t a) {
    unsigned long long v;
    asm volatile("ld.volatile.shared.b64 %0, [%1];" : "=l"(v) : "r"(a) : "memory");
    return v;
}
#define CLUSTER_SYNC() do { \
    asm volatile("barrier.cluster.arrive.aligned;" ::: "memory"); \
    asm volatile("barrier.cluster.wait.aligned;" ::: "memory"); \
} while (0)

// f32x2 packed math
__device__ __forceinline__ unsigned long long f2x2(float a, float b) {
    unsigned long long r;
    asm("mov.b64 %0, {%1, %2};" : "=l"(r) : "r"(__float_as_uint(a)), "r"(__float_as_uint(b)));
    return r;
}
__device__ __forceinline__ unsigned long long add2(unsigned long long a, unsigned long long b) {
    unsigned long long r; asm("add.rn.f32x2 %0, %1, %2;" : "=l"(r) : "l"(a), "l"(b)); return r;
}
__device__ __forceinline__ unsigned long long mul2(unsigned long long a, unsigned long long b) {
    unsigned long long r; asm("mul.rn.f32x2 %0, %1, %2;" : "=l"(r) : "l"(a), "l"(b)); return r;
}
__device__ __forceinline__ unsigned long long fma2(unsigned long long a, unsigned long long b,
                                                   unsigned long long c) {
    unsigned long long r; asm("fma.rn.f32x2 %0, %1, %2, %3;" : "=l"(r) : "l"(a), "l"(b), "l"(c)); return r;
}
__device__ __forceinline__ void unpack2(unsigned long long v, float& lo, float& hi) {
    uint32_t l, h;
    asm("mov.b64 {%0, %1}, %2;" : "=r"(l), "=r"(h) : "l"(v));
    lo = __uint_as_float(l); hi = __uint_as_float(h);
}

// write-once ring slot: key@0 (release-stored), xyz@16 (one v4.b32 store)
struct __align__(16) RSlot { unsigned long long key; unsigned long long pad; float x, y, z, w; };

// =====================================================================
// ONE fused kernel: FPS -> ball query -> gather/maxpool -> LN+GEMM ->
// cluster sync -> attention.  grid = 8 clusters x 8 CTAs.
// FPS comm: write-once 64-deep DSMEM ring; xyz v4 store + release key;
// all warps volatile-spin on their local slots, one acquire confirm,
// per-warp key scan. ONE __syncthreads per iteration, no drain sync.
// key = (distbits<<32) | (0x7fffffff - idx): u64 max == strict-> + lowest idx.
// =====================================================================
__global__ void __cluster_dims__(FCTAS, 1, 1) __launch_bounds__(FBLK, 1)
fused_kernel(const float* __restrict__ x, const float* __restrict__ coor,
             const float* __restrict__ Wq, const float* __restrict__ Wk,
             const float* __restrict__ gq, const float* __restrict__ bq,
             const float* __restrict__ gk, const float* __restrict__ bk,
             float* __restrict__ out1, float* __restrict__ out2) {
    extern __shared__ float dyn[];
    const int b    = blockIdx.x / FCTAS;
    const int r    = blockIdx.x % FCTAS;
    const int tid  = threadIdx.x;
    const int lane = tid & 31;
    const int wid  = tid >> 5;

    __shared__ unsigned           s_v[16];
    __shared__ int                s_i[16];
    __shared__ unsigned long long s_xy[16];
    __shared__ float              s_z[16];
    __shared__ RSlot              ring[SPTS][FCTAS];   // 16 KB write-once ring
    __shared__ int                fps_loc[SPTS];
    __shared__ float              scoor_loc[SPTS*3];
    __shared__ int                snidx[NS][NS];       // [local sample][neighbor]

    // ---------------- Phase 1: FPS ----------------
    {
        const int gbase = r * SEG + tid * FPT;
        const float* cp = coor + ((size_t)b * NPTS + gbase) * 3;
        float fl[24];
        {
            const float4* c4 = (const float4*)cp;
#pragma unroll
            for (int i = 0; i < 6; i++) {
                float4 v = c4[i];
                fl[4*i+0] = v.x; fl[4*i+1] = v.y; fl[4*i+2] = v.z; fl[4*i+3] = v.w;
            }
        }
        unsigned long long px2[4], py2[4], pz2[4];
        float dist[FPT];
#pragma unroll
        for (int j = 0; j < 4; j++) {
            px2[j] = f2x2(fl[6*j+0], fl[6*j+3]);
            py2[j] = f2x2(fl[6*j+1], fl[6*j+4]);
            pz2[j] = f2x2(fl[6*j+2], fl[6*j+5]);
        }
#pragma unroll
        for (int i = 0; i < FPT; i++) dist[i] = 1e10f;

        ring[tid >> 3][tid & 7].key = 0ull;    // 512 threads = all 512 sentinels
        __syncthreads();
        CLUSTER_SYNC();           // sentinel init visible before any peer push

        float cx = coor[(size_t)b*NPTS*3 + 0];
        float cy = coor[(size_t)b*NPTS*3 + 1];
        float cz = coor[(size_t)b*NPTS*3 + 2];
        int far = 0;

        for (int it = 0; it < SPTS; it++) {
            if (tid == 0) {                  // every CTA records locally
                fps_loc[it] = far;
                scoor_loc[it*3+0] = cx;
                scoor_loc[it*3+1] = cy;
                scoor_loc[it*3+2] = cz;
            }
            if (it == SPTS - 1) break;

            const unsigned long long ncx = f2x2(-cx, -cx);
            const unsigned long long ncy = f2x2(-cy, -cy);
            const unsigned long long ncz = f2x2(-cz, -cz);

            float bv = -1.0f;
            int   bi = 0;
#pragma unroll
            for (int j = 0; j < 4; j++) {
                unsigned long long dx = add2(px2[j], ncx);
                unsigned long long dy = add2(py2[j], ncy);
                unsigned long long dz = add2(pz2[j], ncz);
                unsigned long long d2 = mul2(dx, dx);
                d2 = fma2(dy, dy, d2);
                d2 = fma2(dz, dz, d2);
                float lo, hi;
                unpack2(d2, lo, hi);
                float nd0 = fminf(dist[2*j],   lo); dist[2*j]   = nd0;
                if (nd0 > bv) { bv = nd0; bi = 2*j; }
                float nd1 = fminf(dist[2*j+1], hi); dist[2*j+1] = nd1;
                if (nd1 > bv) { bv = nd1; bi = 2*j+1; }
            }
            // warp argmax: dist>=0, float bits monotone; lowest lane = lowest idx
            unsigned vb   = __float_as_uint(bv);
            unsigned vmax = __reduce_max_sync(0xffffffffu, vb);
            unsigned mk   = __ballot_sync(0xffffffffu, vb == vmax);
            if (lane == __ffs(mk) - 1) {
                int jj = bi >> 1, h = bi & 1;
                unsigned long long mx2 = (jj & 2) ? ((jj & 1) ? px2[3] : px2[2]) : ((jj & 1) ? px2[1] : px2[0]);
                unsigned long long my2 = (jj & 2) ? ((jj & 1) ? py2[3] : py2[2]) : ((jj & 1) ? py2[1] : py2[0]);
                unsigned long long mz2 = (jj & 2) ? ((jj & 1) ? pz2[3] : pz2[2]) : ((jj & 1) ? pz2[1] : pz2[0]);
                float xl, xh, yl, yh, zl, zh;
                unpack2(mx2, xl, xh); unpack2(my2, yl, yh); unpack2(mz2, zl, zh);
                s_v[wid]  = vmax;
                s_i[wid]  = gbase + bi;
                s_xy[wid] = f2x2(h ? xh : xl, h ? yh : yl);
                s_z[wid]  = h ? zh : zl;
            }
            __syncthreads();                 // the ONLY barrier per iteration

            if (wid == 0) {
                unsigned v  = (lane < 16) ? s_v[lane] : 0u;
                unsigned vm = __reduce_max_sync(0xffffffffu, v);
                unsigned m2 = __ballot_sync(0xffffffffu, v == vm);
                int s2 = __ffs(m2) - 1;      // lowest warp = lowest idx
                if (lane < FCTAS) {
                    unsigned long long key =
                        ((unsigned long long)vm << 32) | (unsigned)(0x7fffffff - s_i[s2]);
                    float fx, fy; unpack2(s_xy[s2], fx, fy);
                    float fz = s_z[s2];
                    uint32_t la = smem_u32(&ring[it][r]);
                    uint32_t ra = mapa_rank(la, lane);
                    asm volatile("st.shared::cluster.v4.b32 [%0], {%1, %2, %3, %4};"
                                 :: "r"(ra + 16), "f"(fx), "f"(fy), "f"(fz), "f"(0.0f)
                                 : "memory");
                    st_cluster_release_b64(ra, key);   // orders the xyz store
                }
            }
            // all warps self-gate: volatile spin (29-cyc granularity), acquire confirm
            if (lane < FCTAS) {
                uint32_t pa = smem_u32(&ring[it][lane].key);
                while (ld_volatile_b64(pa) == 0ull) { }
                (void)ld_acquire_b64(pa);    // synchronizes-with the release store
            }
            __syncwarp();                    // propagates acquire ordering warp-wide

            // per-thread scan of 8 keys (u64 max) — barrier-free
            unsigned long long bk = ring[it][0].key;
            int bs_ = 0;
#pragma unroll
            for (int rr = 1; rr < FCTAS; rr++) {
                unsigned long long k2 = ring[it][rr].key;
                if (k2 > bk) { bk = k2; bs_ = rr; }
            }
            far = 0x7fffffff - (int)(unsigned)bk;
            cx = ring[it][bs_].x;
            cy = ring[it][bs_].y;
            cz = ring[it][bs_].z;
        }
        // no drain sync: ring slots are write-once and never reused
    }
    __syncthreads();

    // ---------------- Phase 2: ball query (warp w -> sample r*8+w) ----------------
    const float* cb = coor + (size_t)b * NPTS * 3;
    if (wid < NS) {
        const int sl = r * NS + wid;
        const float cx = scoor_loc[sl*3+0], cy = scoor_loc[sl*3+1], cz = scoor_loc[sl*3+2];
        int cnt = 0;
        int nbr[NS];
        for (int jb = 0; jb < NPTS && cnt < NS; jb += 32) {
            int j = jb + lane;
            float dx = cb[j*3+0] - cx;
            float dy = cb[j*3+1] - cy;
            float dz = cb[j*3+2] - cz;
            float d2 = dx*dx + dy*dy + dz*dz;
            unsigned m = __ballot_sync(~0u, d2 < R2);
            while (m && cnt < NS) {
                int bit = __ffs(m) - 1;
                nbr[cnt++] = jb + bit;
                m &= m - 1;
            }
        }
        if (lane == 0) {
            if (cnt == 0) { nbr[0] = 0; cnt = 1; }
            int f = nbr[0];
            for (int i2 = cnt; i2 < NS; i2++) nbr[i2] = f;
#pragma unroll
            for (int i2 = 0; i2 < NS; i2++) snidx[wid][i2] = nbr[i2];
        }
        __syncwarp();
        if (lane < NS) {                     // diff_coor mean
            int nj = snidx[wid][lane];
            float ax = cb[nj*3+0] - cx;
            float ay = cb[nj*3+1] - cy;
            float az = cb[nj*3+2] - cz;
#pragma unroll
            for (int off = 4; off > 0; off >>= 1) {
                ax += __shfl_down_sync(0xffu, ax, off);
                ay += __shfl_down_sync(0xffu, ay, off);
                az += __shfl_down_sync(0xffu, az, off);
            }
            if (lane == 0) {
                int bs = b * SPTS + sl;
                g_dcoor[bs*3+0] = ax * 0.125f;
                g_dcoor[bs*3+1] = ay * 0.125f;
                g_dcoor[bs*3+2] = az * 0.125f;
            }
        }
    }
    __syncthreads();

    // ---------------- Phase 3: gather + maxpool ----------------
    {
        const float* xb = x + (size_t)b * NPTS * DIM;
#pragma unroll
        for (int rd = 0; rd < 4; rd++) {
            int u  = rd * FBLK + tid;
            int si = u >> 8;
            int c  = u & 255;
            int sl = r * NS + si;
            float sx = xb[(size_t)fps_loc[sl] * DIM + c];
            float m = -3.402823466e38f;
#pragma unroll
            for (int t2 = 0; t2 < NS; t2++)
                m = fmaxf(m, xb[(size_t)snidx[si][t2] * DIM + c]);
            out1[(b * SPTS + sl) * DIM + c] = m;   // sample_x + diff_x == global_x
            dyn[SD_OFF + si*DIM + c] = m - sx;
            dyn[SS_OFF + si*DIM + c] = sx;
        }
    }
    __syncthreads();

    // ---------------- Phase 4: LN + GEMM (half 0 = q, half 1 = k) ----------------
    {
        const int half = tid >> 8;
        const int t    = tid & 255;
        float* src = dyn + (half ? SS_OFF : SD_OFF);
        const float* W  = half ? Wk : Wq;
        const float* gg = half ? gk : gq;
        const float* bb = half ? bk : bq;

        {
            const int w = t >> 5, ln = t & 31;
            float4* r4 = (float4*)(src + w * DIM);
            float4 v0 = r4[ln*2], v1 = r4[ln*2+1];
            float sum = v0.x+v0.y+v0.z+v0.w + v1.x+v1.y+v1.z+v1.w;
            float sq  = v0.x*v0.x+v0.y*v0.y+v0.z*v0.z+v0.w*v0.w
                      + v1.x*v1.x+v1.y*v1.y+v1.z*v1.z+v1.w*v1.w;
#pragma unroll
            for (int off = 16; off > 0; off >>= 1) {
                sum += __shfl_xor_sync(~0u, sum, off);
                sq  += __shfl_xor_sync(~0u, sq,  off);
            }
            float mean = sum * (1.0f/256.0f);
            float var  = sq * (1.0f/256.0f) - mean * mean;
            float inv  = rsqrtf(var + 1e-5f);
            const float4* g4 = (const float4*)gg;
            const float4* b4 = (const float4*)bb;
            float4 G0 = g4[ln*2], G1 = g4[ln*2+1];
            float4 B0 = b4[ln*2], B1 = b4[ln*2+1];
            v0.x = (v0.x-mean)*inv*G0.x + B0.x;  v0.y = (v0.y-mean)*inv*G0.y + B0.y;
            v0.z = (v0.z-mean)*inv*G0.z + B0.z;  v0.w = (v0.w-mean)*inv*G0.w + B0.w;
            v1.x = (v1.x-mean)*inv*G1.x + B1.x;  v1.y = (v1.y-mean)*inv*G1.y + B1.y;
            v1.z = (v1.z-mean)*inv*G1.z + B1.z;  v1.w = (v1.w-mean)*inv*G1.w + B1.w;
            r4[ln*2]   = v0;
            r4[ln*2+1] = v1;
        }
        __syncthreads();

        const float4* W4 = (const float4*)(W + t * DIM);
        const float4* A4 = (const float4*)src;
        float acc[8] = {0,0,0,0,0,0,0,0};
#pragma unroll 8
        for (int c4 = 0; c4 < 64; c4++) {
            float4 w = W4[c4];
#pragma unroll
            for (int rr = 0; rr < 8; rr++) {
                float4 a = A4[rr*64 + c4];
                acc[rr] += a.x*w.x + a.y*w.y + a.z*w.z + a.w*w.w;
            }
        }
        if (half == 0) {
#pragma unroll
            for (int rr = 0; rr < 8; rr++)
                dyn[SQ_OFF + rr*DIM + t] = acc[rr];  // q stays in smem
        } else {
            float4* o = (float4*)(g_kT + ((size_t)b * DIM + t) * SPTS + r * 8);
            o[0] = make_float4(acc[0], acc[1], acc[2], acc[3]);
            o[1] = make_float4(acc[4], acc[5], acc[6], acc[7]);
        }
    }
    __threadfence();
    CLUSTER_SYNC();        // g_kT / g_dcoor visible cluster-wide

    // ---------------- Phase 5: attention for rows r*8..r*8+7 ----------------
    {
        float* kts   = dyn + KT_OFF;
        float* sq    = dyn + SQ_OFF;
        float* vs    = dyn + VS_OFF;
        float* s_att = dyn + AT_OFF;

        __syncthreads();
        {
            const float4* ksrc = (const float4*)(g_kT + (size_t)b * DIM * SPTS);
            float4* kdst = (float4*)kts;
#pragma unroll
            for (int i = 0; i < 8; i++)
                kdst[tid + FBLK*i] = ksrc[tid + FBLK*i];
        }
        // v[b,i,j] = diff_coor[b,(3i+j)%64,(3i+j)/64] (torch view reinterp)
        if (tid < 192) vs[tid] = g_dcoor[(b*SPTS + (tid & 63))*3 + (tid >> 6)];
        __syncthreads();

        const int j  = tid & 63;
        const int r2 = tid >> 6;
        const float* qr = sq + r2 * DIM;
        float a = 0.f;
#pragma unroll 8
        for (int c = 0; c < 256; c++)
            a += qr[c] * kts[c*64 + j];
        s_att[r2*64 + j] = a * 0.0625f;      // 1/sqrt(256)
        __syncthreads();

        if (wid < 8) {
            const int row = wid;
            float x0 = s_att[row*64 + lane];
            float x1 = s_att[row*64 + lane + 32];
            float mx = fmaxf(x0, x1);
#pragma unroll
            for (int off = 16; off > 0; off >>= 1) mx = fmaxf(mx, __shfl_xor_sync(~0u, mx, off));
            float e0 = expf(x0 - mx), e1 = expf(x1 - mx);
            float ssum = e0 + e1;
#pragma unroll
            for (int off = 16; off > 0; off >>= 1) ssum += __shfl_xor_sync(~0u, ssum, off);
            float rinv = 1.0f / ssum;
            float p0 = e0 * rinv, p1 = e1 * rinv;
            float c0 = p0 * vs[lane*3+0] + p1 * vs[(lane+32)*3+0];
            float c1 = p0 * vs[lane*3+1] + p1 * vs[(lane+32)*3+1];
            float c2 = p0 * vs[lane*3+2] + p1 * vs[(lane+32)*3+2];
#pragma unroll
            for (int off = 16; off > 0; off >>= 1) {
                c0 += __shfl_xor_sync(~0u, c0, off);
                c1 += __shfl_xor_sync(~0u, c1, off);
                c2 += __shfl_xor_sync(~0u, c2, off);
            }
            if (lane == 0) {
                int sl   = r * 8 + row;
                int rowg = b * SPTS + sl;
                out2[rowg*3+0] = scoor_loc[sl*3+0] + c0;
                out2[rowg*3+1] = scoor_loc[sl*3+1] + c1;
                out2[rowg*3+2] = scoor_loc[sl*3+2] + c2;
            }
        }
    }
}

// ---------------- launcher ----------------
extern "C" void kernel_launch(void* const* d_in, const int* in_sizes, int n_in,
                              void* d_out, int out_size) {
    const float* x    = (const float*)d_in[0];
    const float* coor = (const float*)d_in[1];
    const float* Wq   = (const float*)d_in[2];
    const float* Wk   = (const float*)d_in[3];
    const float* lnqg = (const float*)d_in[4];
    const float* lnqb = (const float*)d_in[5];
    const float* lnkg = (const float*)d_in[6];
    const float* lnkb = (const float*)d_in[7];

    float* out1 = (float*)d_out;                 // [8,64,256]
    float* out2 = out1 + BATCH * SPTS * DIM;     // [8,64,3]

    cudaFuncSetAttribute(fused_kernel, cudaFuncAttributeMaxDynamicSharedMemorySize,
                         DYN_BYTES);

    fused_kernel<<<BATCH * FCTAS, FBLK, DYN_BYTES>>>(
        x, coor, Wq, Wk, lnqg, lnqb, lnkg, lnkb, out1, out2);
}

// round 10
// speedup vs baseline: 1.0554x; 1.0554x over previous
#include <cuda_runtime.h>
#include <cstdint>

#define BATCH 8
#define NPTS  32768
#define DIM   256
#define SPTS  64
#define NS    8
#define R2    16.0f
#define FCTAS 8                 // CTAs per batch (cluster size)
#define SEG   (NPTS/FCTAS)      // 4096 points per CTA
#define FBLK  512
#define FPT   (SEG/FBLK)        // 8 points per thread

// ---------------- scratch (no allocations allowed) ----------------
__device__ float g_dcoor[BATCH*SPTS*3];
__device__ float g_kT[BATCH*DIM*SPTS];   // k transposed: [b][c][j]

// dynamic smem layout (floats)
#define SQ_OFF   0                        // sq[8][256]
#define RA_OFF   (8*DIM)                  // region A: sdiff/ssamp, later kts[256][64]
#define SD_OFF   RA_OFF                   // sdiff[8][256]
#define SS_OFF   (RA_OFF + 8*DIM)         // ssamp[8][256]
#define KT_OFF   RA_OFF                   // kts[256][64] (aliases sdiff/ssamp)
#define VS_OFF   (RA_OFF + DIM*SPTS)      // vs[192]
#define AT_OFF   (VS_OFF + 192)           // s_att[8][64]
#define DYN_FLOATS (AT_OFF + 8*64)
#define DYN_BYTES  (DYN_FLOATS * 4)

// ---------------- PTX helpers ----------------
__device__ __forceinline__ uint32_t smem_u32(const void* p) {
    uint32_t a;
    asm("{ .reg .u64 t; cvta.to.shared.u64 t, %1; cvt.u32.u64 %0, t; }" : "=r"(a) : "l"(p));
    return a;
}
__device__ __forceinline__ uint32_t mapa_rank(uint32_t a, uint32_t r) {
    uint32_t o;
    asm("mapa.shared::cluster.u32 %0, %1, %2;" : "=r"(o) : "r"(a), "r"(r));
    return o;
}
__device__ __forceinline__ void st_cluster_release_b64(uint32_t a, unsigned long long v) {
    asm volatile("st.release.cluster.shared::cluster.b64 [%0], %1;" :: "r"(a), "l"(v) : "memory");
}
__device__ __forceinline__ unsigned long long ld_acquire_b64(uint32_t a) {
    unsigned long long v;
    asm volatile("ld.acquire.cluster.shared::cta.b64 %0, [%1];" : "=l"(v) : "r"(a) : "memory");
    return v;
}
#define CLUSTER_SYNC() do { \
    asm volatile("barrier.cluster.arrive.aligned;" ::: "memory"); \
    asm volatile("barrier.cluster.wait.aligned;" ::: "memory"); \
} while (0)

// f32x2 packed math
__device__ __forceinline__ unsigned long long f2x2(float a, float b) {
    unsigned long long r;
    asm("mov.b64 %0, {%1, %2};" : "=l"(r) : "r"(__float_as_uint(a)), "r"(__float_as_uint(b)));
    return r;
}
__device__ __forceinline__ unsigned long long add2(unsigned long long a, unsigned long long b) {
    unsigned long long r; asm("add.rn.f32x2 %0, %1, %2;" : "=l"(r) : "l"(a), "l"(b)); return r;
}
__device__ __forceinline__ unsigned long long mul2(unsigned long long a, unsigned long long b) {
    unsigned long long r; asm("mul.rn.f32x2 %0, %1, %2;" : "=l"(r) : "l"(a), "l"(b)); return r;
}
__device__ __forceinline__ unsigned long long fma2(unsigned long long a, unsigned long long b,
                                                   unsigned long long c) {
    unsigned long long r; asm("fma.rn.f32x2 %0, %1, %2, %3;" : "=l"(r) : "l"(a), "l"(b), "l"(c)); return r;
}
__device__ __forceinline__ void unpack2(unsigned long long v, float& lo, float& hi) {
    uint32_t l, h;
    asm("mov.b64 {%0, %1}, %2;" : "=r"(l), "=r"(h) : "l"(v));
    lo = __uint_as_float(l); hi = __uint_as_float(h);
}

// write-once ring slot: key@0 (release-stored), xyz@16 (one v4.b32 store)
struct __align__(16) RSlot { unsigned long long key; unsigned long long pad; float x, y, z, w; };

// =====================================================================
// ONE fused kernel: FPS -> ball query -> gather/maxpool -> LN+GEMM ->
// cluster sync -> attention.  grid = 8 clusters x 8 CTAs.
// FPS: warps post winners via volatile stores + flag ring (bit31 marker),
// park at the single barrier; warp0 alone polls flags, reduces, pushes
// (v4 xyz + release key into write-once DSMEM ring), acquire-polls the 8
// peer keys, scans, publishes far/center; barrier releases everyone.
// key = (distbits<<32) | (0x7fffffff - idx): u64 max == strict-> + lowest idx.
// =====================================================================
__global__ void __cluster_dims__(FCTAS, 1, 1) __launch_bounds__(FBLK, 1)
fused_kernel(const float* __restrict__ x, const float* __restrict__ coor,
             const float* __restrict__ Wq, const float* __restrict__ Wk,
             const float* __restrict__ gq, const float* __restrict__ bq,
             const float* __restrict__ gk, const float* __restrict__ bk,
             float* __restrict__ out1, float* __restrict__ out2) {
    extern __shared__ float dyn[];
    const int b    = blockIdx.x / FCTAS;
    const int r    = blockIdx.x % FCTAS;
    const int tid  = threadIdx.x;
    const int lane = tid & 31;
    const int wid  = tid >> 5;

    __shared__ volatile unsigned           s_vflag[SPTS][16];  // flag ring (bit31 = ready)
    __shared__ volatile int                s_i[16];
    __shared__ volatile unsigned long long s_xy[16];
    __shared__ volatile float              s_z[16];
    __shared__ RSlot              ring[SPTS][FCTAS];   // 16 KB write-once DSMEM ring
    __shared__ int                s_bfar;
    __shared__ float              s_bc[3];
    __shared__ int                fps_loc[SPTS];
    __shared__ float              scoor_loc[SPTS*3];
    __shared__ int                snidx[NS][NS];       // [local sample][neighbor]

    // ---------------- Phase 1: FPS ----------------
    {
        const int gbase = r * SEG + tid * FPT;
        const float* cp = coor + ((size_t)b * NPTS + gbase) * 3;
        float fl[24];
        {
            const float4* c4 = (const float4*)cp;
#pragma unroll
            for (int i = 0; i < 6; i++) {
                float4 v = c4[i];
                fl[4*i+0] = v.x; fl[4*i+1] = v.y; fl[4*i+2] = v.z; fl[4*i+3] = v.w;
            }
        }
        unsigned long long px2[4], py2[4], pz2[4];
        float dist[FPT];
#pragma unroll
        for (int j = 0; j < 4; j++) {
            px2[j] = f2x2(fl[6*j+0], fl[6*j+3]);
            py2[j] = f2x2(fl[6*j+1], fl[6*j+4]);
            pz2[j] = f2x2(fl[6*j+2], fl[6*j+5]);
        }
#pragma unroll
        for (int i = 0; i < FPT; i++) dist[i] = 1e10f;

        ring[tid >> 3][tid & 7].key = 0ull;      // 512 ring sentinels
#pragma unroll
        for (int i = 0; i < 2; i++) {            // 1024 flag sentinels
            int u = i * FBLK + tid;
            s_vflag[u >> 4][u & 15] = 0u;
        }
        __syncthreads();
        CLUSTER_SYNC();           // sentinel init visible before any peer push

        float cx = coor[(size_t)b*NPTS*3 + 0];
        float cy = coor[(size_t)b*NPTS*3 + 1];
        float cz = coor[(size_t)b*NPTS*3 + 2];
        int far = 0;

        for (int it = 0; it < SPTS; it++) {
            if (tid == 0) {                  // every CTA records locally
                fps_loc[it] = far;
                scoor_loc[it*3+0] = cx;
                scoor_loc[it*3+1] = cy;
                scoor_loc[it*3+2] = cz;
            }
            if (it == SPTS - 1) break;

            const unsigned long long ncx = f2x2(-cx, -cx);
            const unsigned long long ncy = f2x2(-cy, -cy);
            const unsigned long long ncz = f2x2(-cz, -cz);

            float bm = -1.0f;
#pragma unroll
            for (int j = 0; j < 4; j++) {
                unsigned long long dx = add2(px2[j], ncx);
                unsigned long long dy = add2(py2[j], ncy);
                unsigned long long dz = add2(pz2[j], ncz);
                unsigned long long d2 = mul2(dx, dx);
                d2 = fma2(dy, dy, d2);
                d2 = fma2(dz, dz, d2);
                float lo, hi;
                unpack2(d2, lo, hi);
                float nd0 = fminf(dist[2*j],   lo); dist[2*j]   = nd0;
                float nd1 = fminf(dist[2*j+1], hi); dist[2*j+1] = nd1;
                bm = fmaxf(bm, fmaxf(nd0, nd1));
            }
            // deferred index recovery: downward scan, last write = lowest index
            int bi = 0;
#pragma unroll
            for (int i = 7; i >= 0; i--)
                if (dist[i] == bm) bi = i;

            // warp argmax: dist>=0, float bits monotone; lowest lane = lowest idx
            unsigned vb   = __float_as_uint(bm);
            unsigned vmax = __reduce_max_sync(0xffffffffu, vb);
            unsigned mk   = __ballot_sync(0xffffffffu, vb == vmax);
            if (lane == __ffs(mk) - 1) {
                int jj = bi >> 1, h = bi & 1;
                unsigned long long mx2 = (jj & 2) ? ((jj & 1) ? px2[3] : px2[2]) : ((jj & 1) ? px2[1] : px2[0]);
                unsigned long long my2 = (jj & 2) ? ((jj & 1) ? py2[3] : py2[2]) : ((jj & 1) ? py2[1] : py2[0]);
                unsigned long long mz2 = (jj & 2) ? ((jj & 1) ? pz2[3] : pz2[2]) : ((jj & 1) ? pz2[1] : pz2[0]);
                float xl, xh, yl, yh, zl, zh;
                unpack2(mx2, xl, xh); unpack2(my2, yl, yh); unpack2(mz2, zl, zh);
                // volatile stores in program order; flag LAST (bit31 marker)
                s_i[wid]  = gbase + bi;
                s_xy[wid] = f2x2(h ? xh : xl, h ? yh : yl);
                s_z[wid]  = h ? zh : zl;
                s_vflag[it][wid] = vmax | 0x80000000u;
            }

            if (wid == 0) {
                // gather 16 warp flags (warp0-only polling; others park at bar)
                unsigned f = 0;
                if (lane < 16) {
                    while ((((f = s_vflag[it][lane])) & 0x80000000u) == 0u) { }
                }
                __syncwarp();
                unsigned v  = (lane < 16) ? (f & 0x7fffffffu) : 0u;
                unsigned vm = __reduce_max_sync(0xffffffffu, v);
                unsigned m2 = __ballot_sync(0xffffffffu, v == vm);
                int s2 = __ffs(m2) - 1;      // lowest warp = lowest idx
                if (lane < FCTAS) {
                    unsigned long long key =
                        ((unsigned long long)vm << 32) | (unsigned)(0x7fffffff - s_i[s2]);
                    float fx, fy; unpack2(s_xy[s2], fx, fy);
                    float fz = s_z[s2];
                    uint32_t la = smem_u32((const void*)&ring[it][r]);
                    uint32_t ra = mapa_rank(la, lane);
                    asm volatile("st.shared::cluster.v4.b32 [%0], {%1, %2, %3, %4};"
                                 :: "r"(ra + 16), "f"(fx), "f"(fy), "f"(fz), "f"(0.0f)
                                 : "memory");
                    st_cluster_release_b64(ra, key);   // orders the xyz store
                }
                // acquire-poll the 8 peer keys (the key store IS the signal)
                uint32_t pa = smem_u32((const void*)&ring[it][lane & 7]);
                unsigned long long kk = 1;
                do {
                    if (lane < FCTAS) kk = ld_acquire_b64(pa);
                } while (!__all_sync(0xffffffffu, kk != 0ull));
                __syncwarp();
                if (lane == 0) {
                    unsigned long long bk = ring[it][0].key;
                    int bs_ = 0;
#pragma unroll
                    for (int rr = 1; rr < FCTAS; rr++) {
                        unsigned long long k2 = ring[it][rr].key;
                        if (k2 > bk) { bk = k2; bs_ = rr; }
                    }
                    s_bfar  = 0x7fffffff - (int)(unsigned)bk;
                    s_bc[0] = ring[it][bs_].x;
                    s_bc[1] = ring[it][bs_].y;
                    s_bc[2] = ring[it][bs_].z;
                }
            }
            __syncthreads();                 // the ONLY barrier per iteration
            far = s_bfar;
            cx = s_bc[0]; cy = s_bc[1]; cz = s_bc[2];
        }
        // no drain sync: ring slots are write-once and never reused
    }
    __syncthreads();

    // ---------------- Phase 2: ball query (warp w -> sample r*8+w) ----------------
    const float* cb = coor + (size_t)b * NPTS * 3;
    if (wid < NS) {
        const int sl = r * NS + wid;
        const float cx = scoor_loc[sl*3+0], cy = scoor_loc[sl*3+1], cz = scoor_loc[sl*3+2];
        int cnt = 0;
        int nbr[NS];
        for (int jb = 0; jb < NPTS && cnt < NS; jb += 32) {
            int j = jb + lane;
            float dx = cb[j*3+0] - cx;
            float dy = cb[j*3+1] - cy;
            float dz = cb[j*3+2] - cz;
            float d2 = dx*dx + dy*dy + dz*dz;
            unsigned m = __ballot_sync(~0u, d2 < R2);
            while (m && cnt < NS) {
                int bit = __ffs(m) - 1;
                nbr[cnt++] = jb + bit;
                m &= m - 1;
            }
        }
        if (lane == 0) {
            if (cnt == 0) { nbr[0] = 0; cnt = 1; }
            int f = nbr[0];
            for (int i2 = cnt; i2 < NS; i2++) nbr[i2] = f;
#pragma unroll
            for (int i2 = 0; i2 < NS; i2++) snidx[wid][i2] = nbr[i2];
        }
        __syncwarp();
        if (lane < NS) {                     // diff_coor mean
            int nj = snidx[wid][lane];
            float ax = cb[nj*3+0] - cx;
            float ay = cb[nj*3+1] - cy;
            float az = cb[nj*3+2] - cz;
#pragma unroll
            for (int off = 4; off > 0; off >>= 1) {
                ax += __shfl_down_sync(0xffu, ax, off);
                ay += __shfl_down_sync(0xffu, ay, off);
                az += __shfl_down_sync(0xffu, az, off);
            }
            if (lane == 0) {
                int bs = b * SPTS + sl;
                g_dcoor[bs*3+0] = ax * 0.125f;
                g_dcoor[bs*3+1] = ay * 0.125f;
                g_dcoor[bs*3+2] = az * 0.125f;
            }
        }
    }
    __syncthreads();

    // ---------------- Phase 3: gather + maxpool ----------------
    {
        const float* xb = x + (size_t)b * NPTS * DIM;
#pragma unroll
        for (int rd = 0; rd < 4; rd++) {
            int u  = rd * FBLK + tid;
            int si = u >> 8;
            int c  = u & 255;
            int sl = r * NS + si;
            float sx = xb[(size_t)fps_loc[sl] * DIM + c];
            float m = -3.402823466e38f;
#pragma unroll
            for (int t2 = 0; t2 < NS; t2++)
                m = fmaxf(m, xb[(size_t)snidx[si][t2] * DIM + c]);
            out1[(b * SPTS + sl) * DIM + c] = m;   // sample_x + diff_x == global_x
            dyn[SD_OFF + si*DIM + c] = m - sx;
            dyn[SS_OFF + si*DIM + c] = sx;
        }
    }
    __syncthreads();

    // ---------------- Phase 4: LN + GEMM (half 0 = q, half 1 = k) ----------------
    {
        const int half = tid >> 8;
        const int t    = tid & 255;
        float* src = dyn + (half ? SS_OFF : SD_OFF);
        const float* W  = half ? Wk : Wq;
        const float* gg = half ? gk : gq;
        const float* bb = half ? bk : bq;

        {
            const int w = t >> 5, ln = t & 31;
            float4* r4 = (float4*)(src + w * DIM);
            float4 v0 = r4[ln*2], v1 = r4[ln*2+1];
            float sum = v0.x+v0.y+v0.z+v0.w + v1.x+v1.y+v1.z+v1.w;
            float sq  = v0.x*v0.x+v0.y*v0.y+v0.z*v0.z+v0.w*v0.w
                      + v1.x*v1.x+v1.y*v1.y+v1.z*v1.z+v1.w*v1.w;
#pragma unroll
            for (int off = 16; off > 0; off >>= 1) {
                sum += __shfl_xor_sync(~0u, sum, off);
                sq  += __shfl_xor_sync(~0u, sq,  off);
            }
            float mean = sum * (1.0f/256.0f);
            float var  = sq * (1.0f/256.0f) - mean * mean;
            float inv  = rsqrtf(var + 1e-5f);
            const float4* g4 = (const float4*)gg;
            const float4* b4 = (const float4*)bb;
            float4 G0 = g4[ln*2], G1 = g4[ln*2+1];
            float4 B0 = b4[ln*2], B1 = b4[ln*2+1];
            v0.x = (v0.x-mean)*inv*G0.x + B0.x;  v0.y = (v0.y-mean)*inv*G0.y + B0.y;
            v0.z = (v0.z-mean)*inv*G0.z + B0.z;  v0.w = (v0.w-mean)*inv*G0.w + B0.w;
            v1.x = (v1.x-mean)*inv*G1.x + B1.x;  v1.y = (v1.y-mean)*inv*G1.y + B1.y;
            v1.z = (v1.z-mean)*inv*G1.z + B1.z;  v1.w = (v1.w-mean)*inv*G1.w + B1.w;
            r4[ln*2]   = v0;
            r4[ln*2+1] = v1;
        }
        __syncthreads();

        const float4* W4 = (const float4*)(W + t * DIM);
        const float4* A4 = (const float4*)src;
        float acc[8] = {0,0,0,0,0,0,0,0};
#pragma unroll 8
        for (int c4 = 0; c4 < 64; c4++) {
            float4 w = W4[c4];
#pragma unroll
            for (int rr = 0; rr < 8; rr++) {
                float4 a = A4[rr*64 + c4];
                acc[rr] += a.x*w.x + a.y*w.y + a.z*w.z + a.w*w.w;
            }
        }
        if (half == 0) {
#pragma unroll
            for (int rr = 0; rr < 8; rr++)
                dyn[SQ_OFF + rr*DIM + t] = acc[rr];  // q stays in smem
        } else {
            float4* o = (float4*)(g_kT + ((size_t)b * DIM + t) * SPTS + r * 8);
            o[0] = make_float4(acc[0], acc[1], acc[2], acc[3]);
            o[1] = make_float4(acc[4], acc[5], acc[6], acc[7]);
        }
    }
    __threadfence();
    CLUSTER_SYNC();        // g_kT / g_dcoor visible cluster-wide

    // ---------------- Phase 5: attention for rows r*8..r*8+7 ----------------
    {
        float* kts   = dyn + KT_OFF;
        float* sq    = dyn + SQ_OFF;
        float* vs    = dyn + VS_OFF;
        float* s_att = dyn + AT_OFF;

        __syncthreads();
        {
            const float4* ksrc = (const float4*)(g_kT + (size_t)b * DIM * SPTS);
            float4* kdst = (float4*)kts;
#pragma unroll
            for (int i = 0; i < 8; i++)
                kdst[tid + FBLK*i] = ksrc[tid + FBLK*i];
        }
        // v[b,i,j] = diff_coor[b,(3i+j)%64,(3i+j)/64] (torch view reinterp)
        if (tid < 192) vs[tid] = g_dcoor[(b*SPTS + (tid & 63))*3 + (tid >> 6)];
        __syncthreads();

        const int j  = tid & 63;
        const int r2 = tid >> 6;
        const float* qr = sq + r2 * DIM;
        float a = 0.f;
#pragma unroll 8
        for (int c = 0; c < 256; c++)
            a += qr[c] * kts[c*64 + j];
        s_att[r2*64 + j] = a * 0.0625f;      // 1/sqrt(256)
        __syncthreads();

        if (wid < 8) {
            const int row = wid;
            float x0 = s_att[row*64 + lane];
            float x1 = s_att[row*64 + lane + 32];
            float mx = fmaxf(x0, x1);
#pragma unroll
            for (int off = 16; off > 0; off >>= 1) mx = fmaxf(mx, __shfl_xor_sync(~0u, mx, off));
            float e0 = expf(x0 - mx), e1 = expf(x1 - mx);
            float ssum = e0 + e1;
#pragma unroll
            for (int off = 16; off > 0; off >>= 1) ssum += __shfl_xor_sync(~0u, ssum, off);
            float rinv = 1.0f / ssum;
            float p0 = e0 * rinv, p1 = e1 * rinv;
            float c0 = p0 * vs[lane*3+0] + p1 * vs[(lane+32)*3+0];
            float c1 = p0 * vs[lane*3+1] + p1 * vs[(lane+32)*3+1];
            float c2 = p0 * vs[lane*3+2] + p1 * vs[(lane+32)*3+2];
#pragma unroll
            for (int off = 16; off > 0; off >>= 1) {
                c0 += __shfl_xor_sync(~0u, c0, off);
                c1 += __shfl_xor_sync(~0u, c1, off);
                c2 += __shfl_xor_sync(~0u, c2, off);
            }
            if (lane == 0) {
                int sl   = r * 8 + row;
                int rowg = b * SPTS + sl;
                out2[rowg*3+0] = scoor_loc[sl*3+0] + c0;
                out2[rowg*3+1] = scoor_loc[sl*3+1] + c1;
                out2[rowg*3+2] = scoor_loc[sl*3+2] + c2;
            }
        }
    }
}

// ---------------- launcher ----------------
extern "C" void kernel_launch(void* const* d_in, const int* in_sizes, int n_in,
                              void* d_out, int out_size) {
    const float* x    = (const float*)d_in[0];
    const float* coor = (const float*)d_in[1];
    const float* Wq   = (const float*)d_in[2];
    const float* Wk   = (const float*)d_in[3];
    const float* lnqg = (const float*)d_in[4];
    const float* lnqb = (const float*)d_in[5];
    const float* lnkg = (const float*)d_in[6];
    const float* lnkb = (const float*)d_in[7];

    float* out1 = (float*)d_out;                 // [8,64,256]
    float* out2 = out1 + BATCH * SPTS * DIM;     // [8,64,3]

    cudaFuncSetAttribute(fused_kernel, cudaFuncAttributeMaxDynamicSharedMemorySize,
                         DYN_BYTES);

    fused_kernel<<<BATCH * FCTAS, FBLK, DYN_BYTES>>>(
        x, coor, Wq, Wk, lnqg, lnqb, lnkg, lnkb, out1, out2);
}